// round 13
// baseline (speedup 1.0000x reference)
#include <cuda_runtime.h>
#include <cstdint>

// ---------------- problem constants ----------------
#define BB 1024
#define LL 128
#define PP 32
#define SPLITS 16
#define LPER   8                  // l's per split
#define MTILES 8                  // 1024/128
#define NSTAGE 64                 // stages per CTA; stage = K=128 (one l, 4 i's)
#define NBUF   3
#define THREADS 512

// ---------------- device scratch (allocation-free) ----------------
__device__ float    g_partial[SPLITS * BB * LL];   // 8 MB split-K partials
__device__ uint32_t g_Wh[4096 * 2048];             // 32 MB: 64*W fp16 chunk images [chunk][n=128][k=32]

// ---------------- helpers ----------------
__device__ __forceinline__ uint32_t s2u(const void* p) {
    uint32_t a;
    asm("{ .reg .u64 t; cvta.to.shared.u64 t, %1; cvt.u32.u64 %0, t; }" : "=r"(a) : "l"(p));
    return a;
}
// pack two f32 -> f16x2 (lower half = lo, upper = hi)
__device__ __forceinline__ uint32_t pack_f16x2(float lo, float hi) {
    uint32_t r;
    asm("cvt.rn.f16x2.f32 %0, %1, %2;" : "=r"(r) : "f"(hi), "f"(lo));
    return r;
}
__device__ __forceinline__ void cp16(uint32_t sdst, const void* gsrc) {
    asm volatile("cp.async.cg.shared.global [%0], [%1], 16;" :: "r"(sdst), "l"(gsrc));
}
#define CP_COMMIT() asm volatile("cp.async.commit_group;")
#define CP_WAIT(n)  asm volatile("cp.async.wait_group %0;" :: "n"(n))

#define LDSM4(r, a)                                                              \
    asm volatile("ldmatrix.sync.aligned.m8n8.x4.shared.b16 {%0,%1,%2,%3}, [%4];" \
                 : "=r"((r)[0]), "=r"((r)[1]), "=r"((r)[2]), "=r"((r)[3])        \
                 : "r"(a))

__device__ __forceinline__ void mma_acc(float* d, const uint32_t* a, uint32_t b0, uint32_t b1) {
    asm("mma.sync.aligned.m16n8k16.row.col.f32.f16.f16.f32 "
        "{%0,%1,%2,%3},{%4,%5,%6,%7},{%8,%9},{%0,%1,%2,%3};"
        : "+f"(d[0]), "+f"(d[1]), "+f"(d[2]), "+f"(d[3])
        : "r"(a[0]), "r"(a[1]), "r"(a[2]), "r"(a[3]), "r"(b0), "r"(b1));
}

// ---------------- SMEM layout (main kernel) ----------------
// B tile: [n=128][k=128 fp16], 256B rows, 16B-unit XOR swizzle u^(n&7)
#define ROWB    256
#define BMAT_SZ (128 * ROWB)                  // 32768
#define OFF_PS  (NBUF * BMAT_SZ)              // 98304 : float pS[128][33]
#define OFF_CS  (OFF_PS + 128 * 33 * 4)       // float cS[128][9]
#define SMEM_TOTAL (OFF_CS + 128 * 9 * 4)     // 119808 bytes

// =====================================================================
// Prep: W fp32 [131072][128] -> per-chunk [n=128][k=32] fp16(64*W) images
// =====================================================================
__global__ void __launch_bounds__(256) fipp_prep_kernel(const float* __restrict__ W)
{
    __shared__ float s[32][133];
    const int c = blockIdx.x, tid = threadIdx.x;
    const float4* src = (const float4*)(W + (size_t)c * 4096);
    #pragma unroll
    for (int q = 0; q < 4; q++) {
        const int e = q * 256 + tid;
        float4 v = src[e];
        int j = e >> 5, n4 = (e & 31) << 2;
        s[j][n4] = v.x; s[j][n4 + 1] = v.y; s[j][n4 + 2] = v.z; s[j][n4 + 3] = v.w;
    }
    __syncthreads();
    uint32_t* oh = g_Wh + (size_t)c * 2048;
    #pragma unroll
    for (int q = 0; q < 8; q++) {
        const int e = q * 256 + tid;
        const int n = e >> 4, jw = e & 15;
        oh[e] = pack_f16x2(64.0f * s[2 * jw][n], 64.0f * s[2 * jw + 1][n]);
    }
}

// =====================================================================
// Main: single fp16 HMMA GEMM. CTA: M=128 batch rows, N=128, K=8192.
// 16 warps, warp tile M=32 x N=32 -> 4 warps/SMSP for latency hiding.
// =====================================================================
__global__ void __launch_bounds__(THREADS, 1)
fipp_mma_kernel(const float* __restrict__ ctrl, const float* __restrict__ pert)
{
    extern __shared__ char smem[];
    float* pS = (float*)(smem + OFF_PS);   // [128][33]
    float* cS = (float*)(smem + OFF_CS);   // [128][9]
    const uint32_t sb = s2u(smem);
    const int tid = threadIdx.x, wid = tid >> 5, lane = tid & 31;
    const int wm = wid & 3, wn = wid >> 2;      // 4 M-bands x 4 N-bands (32x32)
    const int g = lane >> 2, t = lane & 3;
    const int bm0 = blockIdx.x * 128, l_base = blockIdx.y * LPER;

    // one-time p (padded 33) and c (padded 9) loads
    for (int e = tid; e < 128 * 32; e += THREADS) {
        int r = e >> 5, j = e & 31;
        pS[r * 33 + j] = pert[(size_t)(bm0 + r) * PP + j];
    }
    for (int e = tid; e < 128 * 8; e += THREADS) {
        int r = e >> 3, q = e & 7;
        cS[r * 9 + q] = ctrl[(size_t)(bm0 + r) * LL + l_base + q];
    }

    // B stage loader: 4 chunk images -> [n][k=128] tile, swizzled 16B units
    auto issueW = [&](int st, int buf) {
        const int l = st >> 3, i0 = (st & 7) * 4;
        const uint32_t* gh = g_Wh + (size_t)((l_base + l) * 32 + i0) * 2048;
        const uint32_t bbase = sb + (uint32_t)buf * BMAT_SZ;
        #pragma unroll
        for (int q = 0; q < 4; q++) {
            const int e = q * THREADS + tid;    // 0..2047 16B units
            const int c = e >> 9, gi = e & 511;
            const int n = gi >> 2, w4 = gi & 3;
            const int u = ((4 * c + w4) ^ (n & 7));
            cp16(bbase + (uint32_t)(n * ROWB + (u << 4)), gh + 4 * e);
        }
        CP_COMMIT();
    };

    issueW(0, 0);
    issueW(1, 1);
    __syncthreads();   // pS/cS ready

    // per-thread rows (4 rows: wm*32 + rr*8 + g) and resident fp32 p-constants
    int rows[4];
    #pragma unroll
    for (int rr = 0; rr < 4; rr++) rows[rr] = wm * 32 + rr * 8 + g;
    // pc[rr][q]: q -> j = (q>>2)*16 + ((q>>1)&1)*8 + 2t + (q&1)
    float pc[4][8];
    #pragma unroll
    for (int rr = 0; rr < 4; rr++)
        #pragma unroll
        for (int q = 0; q < 8; q++)
            pc[rr][q] = pS[rows[rr] * 33 + ((q >> 2) * 16 + ((q >> 1) & 1) * 8 + 2 * t + (q & 1))];

    float acc[2][4][4];
    #pragma unroll
    for (int m = 0; m < 2; m++)
        #pragma unroll
        for (int nt = 0; nt < 4; nt++)
            #pragma unroll
            for (int k = 0; k < 4; k++) acc[m][nt][k] = 0.f;

    float clv[4];

    // ldmatrix addressing: row base per lane + per-lane swizzle constants
    const int nlocal = ((lane >> 4) << 3) | (lane & 7);
    const int hk = (lane >> 3) & 1;          // 16B k-offset select
    const int sx = lane & 7;                 // swizzle XOR
    const uint32_t rba = (uint32_t)((wn * 32 + nlocal) * ROWB);

    for (int st = 0; st < NSTAGE; st++) {
        const int buf = st % NBUF;
        if (st + 2 < NSTAGE) { CP_WAIT(1); } else { CP_WAIT(0); }
        __syncthreads();
        if (st + 2 < NSTAGE) issueW(st + 2, (st + 2) % NBUF);

        const int l = st >> 3, i0 = (st & 7) * 4;
        if ((st & 7) == 0) {
            #pragma unroll
            for (int rr = 0; rr < 4; rr++) clv[rr] = cS[rows[rr] * 9 + l];
        }
        const uint32_t Bt = sb + (uint32_t)buf * BMAT_SZ + rba;

        // fragment-group loader: group idx gidx = c*2+ks  (N=32 -> 2 LDSM4)
        auto ld_group = [&](int gidx, uint32_t* bh) {
            const uint32_t uu = (uint32_t)(((gidx << 1) + hk) ^ sx) << 4;
            LDSM4(bh,     Bt + uu);
            LDSM4(bh + 4, Bt + (uint32_t)(16 * ROWB) + uu);
        };

        uint32_t bhA[8], bhB[8];
        ld_group(0, bhA);

        float s4[4];
        #pragma unroll
        for (int gidx = 0; gidx < 8; gidx++) {
            const int c = gidx >> 1, ks = gidx & 1;
            uint32_t* cur = (gidx & 1) ? bhB : bhA;
            uint32_t* nxt = (gidx & 1) ? bhA : bhB;
            if (gidx + 1 < 8) ld_group(gidx + 1, nxt);

            if (ks == 0) {
                #pragma unroll
                for (int rr = 0; rr < 4; rr++) s4[rr] = clv[rr] * pS[rows[rr] * 33 + i0 + c];
            }

            // build pre-scaled fp16 A fragments for this (c,ks): 2 M-subtiles
            uint32_t a[2][4];
            #pragma unroll
            for (int m = 0; m < 2; m++)
                #pragma unroll
                for (int r4 = 0; r4 < 4; r4++) {
                    const int rr = 2 * m + (r4 & 1);
                    const int q = ks * 4 + (r4 >> 1) * 2;
                    a[m][r4] = pack_f16x2(s4[rr] * pc[rr][q], s4[rr] * pc[rr][q + 1]);
                }

            #pragma unroll
            for (int m = 0; m < 2; m++)
                #pragma unroll
                for (int nt = 0; nt < 4; nt++)
                    mma_acc(acc[m][nt], a[m], cur[2 * nt], cur[2 * nt + 1]);
        }
    }

    // epilogue -> split-K partials (undo the *64 on W)
    #pragma unroll
    for (int m = 0; m < 2; m++)
        #pragma unroll
        for (int rh = 0; rh < 2; rh++) {
            const int rowloc = wm * 32 + m * 16 + rh * 8 + g;
            float* dst = g_partial + ((size_t)blockIdx.y * BB + bm0 + rowloc) * LL;
            #pragma unroll
            for (int nt = 0; nt < 4; nt++) {
                const int col = wn * 32 + nt * 8 + 2 * t;
                float2 v;
                v.x = acc[m][nt][rh ? 2 : 0] * 0.015625f;
                v.y = acc[m][nt][rh ? 3 : 1] * 0.015625f;
                *(float2*)(dst + col) = v;
            }
        }
}

// =====================================================================
// Reduce: sum 16 split-K partials + bias
// =====================================================================
__global__ void __launch_bounds__(256)
fipp_reduce_kernel(const float* __restrict__ bias, float* __restrict__ out)
{
    const int i4 = blockIdx.x * blockDim.x + threadIdx.x;
    float4 acc = *(const float4*)(bias + ((i4 * 4) & (LL - 1)));
    #pragma unroll
    for (int s = 0; s < SPLITS; s++) {
        const float4 v = *(const float4*)(g_partial + (size_t)s * (BB * LL) + (size_t)i4 * 4);
        acc.x += v.x; acc.y += v.y; acc.z += v.z; acc.w += v.w;
    }
    *(float4*)(out + (size_t)i4 * 4) = acc;
}

extern "C" void kernel_launch(void* const* d_in, const int* in_sizes, int n_in,
                              void* d_out, int out_size)
{
    const float* ctrl = (const float*)d_in[0];   // (1024,128)
    const float* pert = (const float*)d_in[1];   // (1024,32)
    const float* W    = (const float*)d_in[2];   // (131072,128)
    const float* bias = (const float*)d_in[3];   // (128,)
    float* out = (float*)d_out;                  // (1024,128)

    cudaFuncSetAttribute(fipp_mma_kernel,
                         cudaFuncAttributeMaxDynamicSharedMemorySize, SMEM_TOTAL);

    fipp_prep_kernel<<<4096, 256>>>(W);
    fipp_mma_kernel<<<dim3(MTILES, SPLITS), THREADS, SMEM_TOTAL>>>(ctrl, pert);
    fipp_reduce_kernel<<<(BB * LL) / 4 / 256, 256>>>(bias, out);
}

// round 14
// speedup vs baseline: 1.1169x; 1.1169x over previous
#include <cuda_runtime.h>
#include <cstdint>

// ---------------- problem constants ----------------
#define BB 1024
#define LL 128
#define PP 32
#define SPLITS 16
#define LPER   8                  // l's per split
#define MTILES 8                  // 1024/128
#define NSTAGE 32                 // stages per CTA; stage = K=256 (one l-quarter, 8 i's)
#define NBUF   3

// ---------------- device scratch (allocation-free) ----------------
__device__ float    g_partial[SPLITS * BB * LL];   // 8 MB split-K partials
__device__ uint32_t g_Wh[4096 * 2048];             // 32 MB: 64*W fp16 chunk images [chunk][n=128][k=32]

// ---------------- helpers ----------------
__device__ __forceinline__ uint32_t s2u(const void* p) {
    uint32_t a;
    asm("{ .reg .u64 t; cvta.to.shared.u64 t, %1; cvt.u32.u64 %0, t; }" : "=r"(a) : "l"(p));
    return a;
}
// pack two f32 -> f16x2 (lower half = lo, upper = hi)
__device__ __forceinline__ uint32_t pack_f16x2(float lo, float hi) {
    uint32_t r;
    asm("cvt.rn.f16x2.f32 %0, %1, %2;" : "=r"(r) : "f"(hi), "f"(lo));
    return r;
}
__device__ __forceinline__ void cp16(uint32_t sdst, const void* gsrc) {
    asm volatile("cp.async.cg.shared.global [%0], [%1], 16;" :: "r"(sdst), "l"(gsrc));
}
#define CP_COMMIT() asm volatile("cp.async.commit_group;")
#define CP_WAIT(n)  asm volatile("cp.async.wait_group %0;" :: "n"(n))

#define LDSM4(r, a)                                                              \
    asm volatile("ldmatrix.sync.aligned.m8n8.x4.shared.b16 {%0,%1,%2,%3}, [%4];" \
                 : "=r"((r)[0]), "=r"((r)[1]), "=r"((r)[2]), "=r"((r)[3])        \
                 : "r"(a))

__device__ __forceinline__ void mma_acc(float* d, const uint32_t* a, uint32_t b0, uint32_t b1) {
    asm("mma.sync.aligned.m16n8k16.row.col.f32.f16.f16.f32 "
        "{%0,%1,%2,%3},{%4,%5,%6,%7},{%8,%9},{%0,%1,%2,%3};"
        : "+f"(d[0]), "+f"(d[1]), "+f"(d[2]), "+f"(d[3])
        : "r"(a[0]), "r"(a[1]), "r"(a[2]), "r"(a[3]), "r"(b0), "r"(b1));
}

// ---------------- SMEM layout (main kernel) ----------------
// stage buffer = 2 sub-tiles, each [n=128][k=128 fp16] 256B rows,
// 16B-unit XOR swizzle u^(n&7)
#define ROWB    256
#define BMAT_SZ (128 * ROWB)                  // 32768 per sub-tile
#define BUF_SZ  (2 * BMAT_SZ)                 // 65536 per stage buffer
#define OFF_PS  (NBUF * BUF_SZ)               // 196608 : float pS[128][33]
#define OFF_CS  (OFF_PS + 128 * 33 * 4)       // float cS[128][9]
#define SMEM_TOTAL (OFF_CS + 128 * 9 * 4)     // 218112 bytes

// =====================================================================
// Prep: W fp32 [131072][128] -> per-chunk [n=128][k=32] fp16(64*W) images
// =====================================================================
__global__ void __launch_bounds__(256) fipp_prep_kernel(const float* __restrict__ W)
{
    __shared__ float s[32][133];
    const int c = blockIdx.x, tid = threadIdx.x;
    const float4* src = (const float4*)(W + (size_t)c * 4096);
    #pragma unroll
    for (int q = 0; q < 4; q++) {
        const int e = q * 256 + tid;
        float4 v = src[e];
        int j = e >> 5, n4 = (e & 31) << 2;
        s[j][n4]     = 64.0f * v.x; s[j][n4 + 1] = 64.0f * v.y;
        s[j][n4 + 2] = 64.0f * v.z; s[j][n4 + 3] = 64.0f * v.w;
    }
    __syncthreads();
    uint32_t* oh = g_Wh + (size_t)c * 2048;
    #pragma unroll
    for (int v = 0; v < 2; v++) {
        const int idx = v * 256 + tid;          // 0..511 16B output units
        const int n = idx >> 2, jq = idx & 3;
        uint32_t r[4];
        #pragma unroll
        for (int d = 0; d < 4; d++)
            r[d] = pack_f16x2(s[8 * jq + 2 * d][n], s[8 * jq + 2 * d + 1][n]);
        *(uint4*)(oh + n * 16 + jq * 4) = make_uint4(r[0], r[1], r[2], r[3]);
    }
}

// =====================================================================
// Main: single fp16 HMMA GEMM. CTA: M=128 batch rows, N=128, K=8192.
// 8 warps, warp tile M=32 x N=64. K=256 per stage (32 stages) to halve
// per-stage barrier/pipeline overhead.
// =====================================================================
__global__ void __launch_bounds__(256, 1)
fipp_mma_kernel(const float* __restrict__ ctrl, const float* __restrict__ pert)
{
    extern __shared__ char smem[];
    float* pS = (float*)(smem + OFF_PS);   // [128][33]
    float* cS = (float*)(smem + OFF_CS);   // [128][9]
    const uint32_t sb = s2u(smem);
    const int tid = threadIdx.x, wid = tid >> 5, lane = tid & 31;
    const int wm = wid & 3, wn = wid >> 2;   // 4 M-bands x 2 N-bands (32x64)
    const int g = lane >> 2, t = lane & 3;
    const int bm0 = blockIdx.x * 128, l_base = blockIdx.y * LPER;

    // one-time p (padded 33) and c (padded 9) loads
    for (int e = tid; e < 128 * 32; e += 256) {
        int r = e >> 5, j = e & 31;
        pS[r * 33 + j] = pert[(size_t)(bm0 + r) * PP + j];
    }
    for (int e = tid; e < 128 * 8; e += 256) {
        int r = e >> 3, q = e & 7;
        cS[r * 9 + q] = ctrl[(size_t)(bm0 + r) * LL + l_base + q];
    }

    // stage loader: 8 chunk images (64KB) -> two [n][k=128] sub-tiles
    auto issueW = [&](int st, int buf) {
        const int l = st >> 2, i0 = (st & 3) * 8;
        const uint32_t* gh = g_Wh + (size_t)((l_base + l) * 32 + i0) * 2048;
        const uint32_t bbase = sb + (uint32_t)buf * BUF_SZ;
        #pragma unroll
        for (int q = 0; q < 16; q++) {
            const int e = q * 256 + tid;        // 0..4095 16B units
            const int c = e >> 9, gi = e & 511; // c: image 0..7
            const int n = gi >> 2, w4 = gi & 3;
            const int u = ((4 * (c & 3) + w4) ^ (n & 7));
            cp16(bbase + (uint32_t)((c >> 2) * BMAT_SZ + n * ROWB + (u << 4)),
                 gh + 4 * e);
        }
        CP_COMMIT();
    };

    issueW(0, 0);
    issueW(1, 1);
    __syncthreads();   // pS/cS ready

    // per-thread rows (4 rows: wm*32 + rr*8 + g) and resident fp32 p-constants
    int rows[4];
    #pragma unroll
    for (int rr = 0; rr < 4; rr++) rows[rr] = wm * 32 + rr * 8 + g;
    // pc[rr][q]: q -> j = (q>>2)*16 + ((q>>1)&1)*8 + 2t + (q&1)
    float pc[4][8];
    #pragma unroll
    for (int rr = 0; rr < 4; rr++)
        #pragma unroll
        for (int q = 0; q < 8; q++)
            pc[rr][q] = pS[rows[rr] * 33 + ((q >> 2) * 16 + ((q >> 1) & 1) * 8 + 2 * t + (q & 1))];

    float acc[2][8][4];
    #pragma unroll
    for (int m = 0; m < 2; m++)
        #pragma unroll
        for (int nt = 0; nt < 8; nt++)
            #pragma unroll
            for (int k = 0; k < 4; k++) acc[m][nt][k] = 0.f;

    float clv[4];

    // ldmatrix addressing: row base per lane + per-lane swizzle constants
    const int nlocal = ((lane >> 4) << 3) | (lane & 7);
    const int hk = (lane >> 3) & 1;          // 16B k-offset select
    const int sx = lane & 7;                 // swizzle XOR
    const uint32_t rba = (uint32_t)((wn * 64 + nlocal) * ROWB);

    for (int st = 0; st < NSTAGE; st++) {
        const int buf = st % NBUF;
        if (st + 2 < NSTAGE) { CP_WAIT(1); } else { CP_WAIT(0); }
        __syncthreads();
        if (st + 2 < NSTAGE) issueW(st + 2, (st + 2) % NBUF);

        const int l = st >> 2, i0 = (st & 3) * 8;
        if ((st & 3) == 0) {
            #pragma unroll
            for (int rr = 0; rr < 4; rr++) clv[rr] = cS[rows[rr] * 9 + l];
        }
        const uint32_t Bt = sb + (uint32_t)buf * BUF_SZ + rba;

        // fragment-group loader: gidx = c*2+ks, c 0..7; sub-tile = gidx>>3
        auto ld_group = [&](int gidx, uint32_t* bh) {
            const uint32_t base = Bt + (uint32_t)((gidx >> 3) * BMAT_SZ);
            const uint32_t uu = (uint32_t)((((gidx & 7) << 1) + hk) ^ sx) << 4;
            #pragma unroll
            for (int ntp = 0; ntp < 4; ntp++)
                LDSM4(bh + 4 * ntp, base + (uint32_t)(ntp * 16 * ROWB) + uu);
        };

        uint32_t bhA[16], bhB[16];
        ld_group(0, bhA);

        float s4[4];
        #pragma unroll
        for (int gidx = 0; gidx < 16; gidx++) {
            const int c = gidx >> 1, ks = gidx & 1;
            uint32_t* cur = (gidx & 1) ? bhB : bhA;
            uint32_t* nxt = (gidx & 1) ? bhA : bhB;
            if (gidx + 1 < 16) ld_group(gidx + 1, nxt);

            if (ks == 0) {
                #pragma unroll
                for (int rr = 0; rr < 4; rr++) s4[rr] = clv[rr] * pS[rows[rr] * 33 + i0 + c];
            }

            // build pre-scaled fp16 A fragments for this (c,ks): 2 M-subtiles
            uint32_t a[2][4];
            #pragma unroll
            for (int m = 0; m < 2; m++)
                #pragma unroll
                for (int r4 = 0; r4 < 4; r4++) {
                    const int rr = 2 * m + (r4 & 1);
                    const int q = ks * 4 + (r4 >> 1) * 2;
                    a[m][r4] = pack_f16x2(s4[rr] * pc[rr][q], s4[rr] * pc[rr][q + 1]);
                }

            #pragma unroll
            for (int m = 0; m < 2; m++)
                #pragma unroll
                for (int nt = 0; nt < 8; nt++)
                    mma_acc(acc[m][nt], a[m], cur[2 * nt], cur[2 * nt + 1]);
        }
    }

    // epilogue -> split-K partials (undo the *64 on W)
    #pragma unroll
    for (int m = 0; m < 2; m++)
        #pragma unroll
        for (int rh = 0; rh < 2; rh++) {
            const int rowloc = wm * 32 + m * 16 + rh * 8 + g;
            float* dst = g_partial + ((size_t)blockIdx.y * BB + bm0 + rowloc) * LL;
            #pragma unroll
            for (int nt = 0; nt < 8; nt++) {
                const int col = wn * 64 + nt * 8 + 2 * t;
                float2 v;
                v.x = acc[m][nt][rh ? 2 : 0] * 0.015625f;
                v.y = acc[m][nt][rh ? 3 : 1] * 0.015625f;
                *(float2*)(dst + col) = v;
            }
        }
}

// =====================================================================
// Reduce: sum 16 split-K partials + bias
// =====================================================================
__global__ void __launch_bounds__(256)
fipp_reduce_kernel(const float* __restrict__ bias, float* __restrict__ out)
{
    const int i4 = blockIdx.x * blockDim.x + threadIdx.x;
    float4 acc = *(const float4*)(bias + ((i4 * 4) & (LL - 1)));
    #pragma unroll
    for (int s = 0; s < SPLITS; s++) {
        const float4 v = *(const float4*)(g_partial + (size_t)s * (BB * LL) + (size_t)i4 * 4);
        acc.x += v.x; acc.y += v.y; acc.z += v.z; acc.w += v.w;
    }
    *(float4*)(out + (size_t)i4 * 4) = acc;
}

extern "C" void kernel_launch(void* const* d_in, const int* in_sizes, int n_in,
                              void* d_out, int out_size)
{
    const float* ctrl = (const float*)d_in[0];   // (1024,128)
    const float* pert = (const float*)d_in[1];   // (1024,32)
    const float* W    = (const float*)d_in[2];   // (131072,128)
    const float* bias = (const float*)d_in[3];   // (128,)
    float* out = (float*)d_out;                  // (1024,128)

    cudaFuncSetAttribute(fipp_mma_kernel,
                         cudaFuncAttributeMaxDynamicSharedMemorySize, SMEM_TOTAL);

    fipp_prep_kernel<<<4096, 256>>>(W);
    fipp_mma_kernel<<<dim3(MTILES, SPLITS), 256, SMEM_TOTAL>>>(ctrl, pert);
    fipp_reduce_kernel<<<(BB * LL) / 4 / 256, 256>>>(bias, out);
}